// round 1
// baseline (speedup 1.0000x reference)
#include <cuda_runtime.h>
#include <math.h>

// Problem constants
#define Bn   2
#define Cc   64
#define Hh   224
#define Ww   224
#define Kk   3
#define K2   9
#define HW   (Hh*Ww)
#define NOFF 27          // 18 offset channels + 9 mask channels
#define COUT 64
#define Jdim 576         // Cc * K2

// Scratch (device globals — no allocation allowed)
__device__ float g_offmask[Bn*NOFF*HW];   // conv1 output: [b][27][H][W] (mask already sigmoided)
__device__ float g_wT[Jdim*COUT];         // deform weights transposed: [j][co]
__device__ float g_wofT[Jdim*NOFF];       // offset+mask weights transposed: [j][oc]

// ---------------------------------------------------------------------------
// Kernel 0: transpose weights for coalesced GEMM-phase loads
// ---------------------------------------------------------------------------
__global__ void transpose_weights(const float* __restrict__ w_off,
                                  const float* __restrict__ w_mask,
                                  const float* __restrict__ w_def) {
    int idx = blockIdx.x * blockDim.x + threadIdx.x;
    if (idx < Jdim*COUT) {
        int j = idx / COUT, co = idx - j*COUT;
        g_wT[idx] = w_def[co*Jdim + j];
    }
    if (idx < Jdim*NOFF) {
        int j = idx / NOFF, oc = idx - j*NOFF;
        g_wofT[idx] = (oc < 18) ? w_off[oc*Jdim + j] : w_mask[(oc-18)*Jdim + j];
    }
}

// ---------------------------------------------------------------------------
// Kernel 1: offset + mask 3x3 conv (27 output channels), sigmoid on mask chans
// Block: 128 threads, 16 output positions (one ho row segment).
// Phase 1: im2col patch[576][16] into smem. Phase 2: GEMM 27 x 576.
// ---------------------------------------------------------------------------
#define TPA 16
__global__ void __launch_bounds__(128) offmask_conv(
        const float* __restrict__ x,
        const float* __restrict__ b_off,
        const float* __restrict__ b_mask) {
    __shared__ __align__(16) float patch[Jdim*TPA];   // 36 KB

    const int wo0 = blockIdx.x * TPA;
    const int ho  = blockIdx.y;
    const int b   = blockIdx.z;
    const int tid = threadIdx.x;
    const float* xb = x + (size_t)b * Cc * HW;

    // im2col gather
    for (int i = tid; i < Jdim*TPA; i += 128) {
        int pos = i & (TPA-1);
        int j   = i >> 4;
        int c   = j / 9;
        int k   = j - c*9;
        int ky  = k / 3;
        int kx  = k - ky*3;
        int iy  = ho + ky - 1;
        int ix  = wo0 + pos + kx - 1;
        float v = 0.f;
        if (iy >= 0 && iy < Hh && ix >= 0 && ix < Ww)
            v = xb[c*HW + iy*Ww + ix];
        patch[j*TPA + pos] = v;
    }
    __syncthreads();

    const int oc = tid & 31;       // 0..31, valid < 27
    const int pg = tid >> 5;       // 0..3 position group (4 pos each)
    if (oc < NOFF) {
        float4 acc = make_float4(0.f, 0.f, 0.f, 0.f);
        const float* wrow = g_wofT + oc;
        #pragma unroll 8
        for (int j = 0; j < Jdim; j++) {
            float w = wrow[j*NOFF];
            float4 v = *(const float4*)&patch[j*TPA + pg*4];
            acc.x = fmaf(w, v.x, acc.x);
            acc.y = fmaf(w, v.y, acc.y);
            acc.z = fmaf(w, v.z, acc.z);
            acc.w = fmaf(w, v.w, acc.w);
        }
        float bias = (oc < 18) ? b_off[oc] : b_mask[oc-18];
        acc.x += bias; acc.y += bias; acc.z += bias; acc.w += bias;
        if (oc >= 18) {  // sigmoid for mask channels
            acc.x = 1.f / (1.f + __expf(-acc.x));
            acc.y = 1.f / (1.f + __expf(-acc.y));
            acc.z = 1.f / (1.f + __expf(-acc.z));
            acc.w = 1.f / (1.f + __expf(-acc.w));
        }
        *(float4*)&g_offmask[((size_t)b*NOFF + oc)*HW + ho*Ww + wo0 + pg*4] = acc;
    }
}

// ---------------------------------------------------------------------------
// Kernel 2: bilinear gather (zero-padded, mask-modulated) + 64x576 GEMM
// Block: 256 threads, 16 output positions.
// ---------------------------------------------------------------------------
#define TPB 16
__global__ void __launch_bounds__(256) deform_main(
        const float* __restrict__ x,
        float* __restrict__ out) {
    __shared__ __align__(16) float val[Jdim*TPB];   // 36 KB
    __shared__ int    p_y0[K2*TPB];
    __shared__ int    p_x0[K2*TPB];
    __shared__ float4 p_w [K2*TPB];                 // corner weights * mask

    const int wo0 = blockIdx.x * TPB;
    const int ho  = blockIdx.y;
    const int b   = blockIdx.z;
    const int tid = threadIdx.x;

    // Phase 0: per-(k2,pos) bilinear parameters
    if (tid < K2*TPB) {
        int pos = tid & (TPB-1);
        int k2  = tid >> 4;
        const float* om = g_offmask + (size_t)b*NOFF*HW + ho*Ww + wo0 + pos;
        float dy = om[(2*k2    )*HW];
        float dx = om[(2*k2 + 1)*HW];
        float m  = om[(18 + k2 )*HW];
        int ky = k2 / 3;
        int kx = k2 - ky*3;
        float py = dy + (float)(ho  - 1 + ky);
        float px = dx + (float)(wo0 + pos - 1 + kx);
        float fy = floorf(py);
        float fx = floorf(px);
        float wy1 = py - fy, wx1 = px - fx;
        float wy0 = 1.f - wy1, wx0 = 1.f - wx1;
        p_y0[tid] = (int)fy;
        p_x0[tid] = (int)fx;
        p_w [tid] = make_float4(wy0*wx0*m, wy0*wx1*m, wy1*wx0*m, wy1*wx1*m);
    }
    __syncthreads();

    // Phase 1: gather val[c*9+k2][pos]
    const float* xb = x + (size_t)b * Cc * HW;
    for (int i = tid; i < Jdim*TPB; i += 256) {
        int pos = i & (TPB-1);
        int r   = i >> 4;            // 0..575 = c*9 + k2
        int c   = r / 9;
        int k2  = r - c*9;
        int pk  = k2*TPB + pos;
        int y0  = p_y0[pk];
        int x0  = p_x0[pk];
        float4 w = p_w[pk];
        const float* xc = xb + c*HW;
        bool vy0 = (y0   >= 0) && (y0   < Hh);
        bool vy1 = (y0+1 >= 0) && (y0+1 < Hh);
        bool vx0 = (x0   >= 0) && (x0   < Ww);
        bool vx1 = (x0+1 >= 0) && (x0+1 < Ww);
        float v = 0.f;
        if (vy0) {
            const float* row = xc + y0*Ww;
            if (vx0) v = fmaf(w.x, row[x0],   v);
            if (vx1) v = fmaf(w.y, row[x0+1], v);
        }
        if (vy1) {
            const float* row = xc + (y0+1)*Ww;
            if (vx0) v = fmaf(w.z, row[x0],   v);
            if (vx1) v = fmaf(w.w, row[x0+1], v);
        }
        val[r*TPB + pos] = v;
    }
    __syncthreads();

    // Phase 2: out[co][pos] = sum_j wT[j][co] * val[j][pos]
    const int co = tid & 63;
    const int pg = tid >> 6;   // 0..3, 4 pos each
    float4 acc = make_float4(0.f, 0.f, 0.f, 0.f);
    const float* wrow = g_wT + co;
    #pragma unroll 8
    for (int j = 0; j < Jdim; j++) {
        float w = wrow[j*COUT];
        float4 v = *(const float4*)&val[j*TPB + pg*4];
        acc.x = fmaf(w, v.x, acc.x);
        acc.y = fmaf(w, v.y, acc.y);
        acc.z = fmaf(w, v.z, acc.z);
        acc.w = fmaf(w, v.w, acc.w);
    }
    *(float4*)&out[((size_t)b*COUT + co)*HW + ho*Ww + wo0 + pg*4] = acc;
}

// ---------------------------------------------------------------------------
extern "C" void kernel_launch(void* const* d_in, const int* in_sizes, int n_in,
                              void* d_out, int out_size) {
    const float* x      = (const float*)d_in[0];
    const float* w_off  = (const float*)d_in[1];
    const float* b_off  = (const float*)d_in[2];
    const float* w_mask = (const float*)d_in[3];
    const float* b_mask = (const float*)d_in[4];
    const float* w_def  = (const float*)d_in[5];
    float* out = (float*)d_out;

    transpose_weights<<<(Jdim*COUT + 255)/256, 256>>>(w_off, w_mask, w_def);

    dim3 ga(Ww/TPA, Hh, Bn);
    offmask_conv<<<ga, 128>>>(x, b_off, b_mask);

    dim3 gb(Ww/TPB, Hh, Bn);
    deform_main<<<gb, 256>>>(x, out);
}

// round 2
// speedup vs baseline: 1.0249x; 1.0249x over previous
#include <cuda_runtime.h>
#include <math.h>

// Problem constants
#define Bn   2
#define Cc   64
#define Hh   224
#define Ww   224
#define K2   9
#define HW   (Hh*Ww)
#define NOFF 27          // 18 offset channels + 9 mask channels
#define COUT 64
#define Jdim 576         // Cc * K2
#define CHUNK 64
#define NCHUNK (Jdim/CHUNK)   // 9
#define PT   64          // positions per block: 2 rows x 32 cols

// Scratch (device globals — no allocation allowed)
__device__ float g_offmask[Bn*NOFF*HW];   // [b][27][H][W], mask already sigmoided
__device__ float g_wT[Jdim*COUT];         // deform weights transposed: [j][co]
__device__ float g_wofT[Jdim*NOFF];       // offset+mask weights transposed: [j][oc]

// ---------------------------------------------------------------------------
// Kernel 0: transpose weights
// ---------------------------------------------------------------------------
__global__ void transpose_weights(const float* __restrict__ w_off,
                                  const float* __restrict__ w_mask,
                                  const float* __restrict__ w_def) {
    int idx = blockIdx.x * blockDim.x + threadIdx.x;
    if (idx < Jdim*COUT) {
        int j = idx / COUT, co = idx - j*COUT;
        g_wT[idx] = w_def[co*Jdim + j];
    }
    if (idx < Jdim*NOFF) {
        int j = idx / NOFF, oc = idx - j*NOFF;
        g_wofT[idx] = (oc < 18) ? w_off[oc*Jdim + j] : w_mask[(oc-18)*Jdim + j];
    }
}

// ---------------------------------------------------------------------------
// Kernel 1: offset+mask 3x3 conv (27 ch) as chunked smem GEMM.
// Block: 512 threads, 64 positions (2 rows x 32 cols).
// ---------------------------------------------------------------------------
__global__ void __launch_bounds__(512) offmask_conv(
        const float* __restrict__ x,
        const float* __restrict__ b_off,
        const float* __restrict__ b_mask) {
    __shared__ __align__(16) float pbuf[2][CHUNK*PT];   // 2 x 16KB
    __shared__ __align__(16) float wbuf[2][CHUNK*32];   // 2 x  8KB

    const int wo0 = blockIdx.x * 32;
    const int ho0 = blockIdx.y * 2;
    const int b   = blockIdx.z;
    const int tid = threadIdx.x;
    const float* xb = x + (size_t)b * Cc * HW;

    const int oc = tid & 31;       // 0..31 (valid < 27)
    const int pg = tid >> 5;       // 0..15 -> 4 positions each

    float4 acc = make_float4(0.f, 0.f, 0.f, 0.f);

    // Prologue: stage chunk 0
    {
        const int jc = 0;
        #pragma unroll
        for (int i = tid; i < CHUNK*PT; i += 512) {
            int pos = i & 63, jj = i >> 6;
            int j = jc*CHUNK + jj;
            int c = j / 9, k = j - c*9;
            int ky = k/3, kx = k - ky*3;
            int iy = ho0 + (pos>>5) + ky - 1;
            int ix = wo0 + (pos&31) + kx - 1;
            float v = 0.f;
            if (iy >= 0 && iy < Hh && ix >= 0 && ix < Ww)
                v = xb[c*HW + iy*Ww + ix];
            pbuf[0][jj*PT + pos] = v;
        }
        #pragma unroll
        for (int i = tid; i < CHUNK*32; i += 512) {
            int o = i & 31, jj = i >> 5;
            wbuf[0][i] = (o < NOFF) ? g_wofT[(jc*CHUNK + jj)*NOFF + o] : 0.f;
        }
    }
    __syncthreads();

    for (int kc = 0; kc < NCHUNK; kc++) {
        int cb = kc & 1, nb = cb ^ 1;
        if (kc + 1 < NCHUNK) {
            const int jc = kc + 1;
            #pragma unroll
            for (int i = tid; i < CHUNK*PT; i += 512) {
                int pos = i & 63, jj = i >> 6;
                int j = jc*CHUNK + jj;
                int c = j / 9, k = j - c*9;
                int ky = k/3, kx = k - ky*3;
                int iy = ho0 + (pos>>5) + ky - 1;
                int ix = wo0 + (pos&31) + kx - 1;
                float v = 0.f;
                if (iy >= 0 && iy < Hh && ix >= 0 && ix < Ww)
                    v = xb[c*HW + iy*Ww + ix];
                pbuf[nb][jj*PT + pos] = v;
            }
            #pragma unroll
            for (int i = tid; i < CHUNK*32; i += 512) {
                int o = i & 31, jj = i >> 5;
                wbuf[nb][i] = (o < NOFF) ? g_wofT[((jc*CHUNK)+jj)*NOFF + o] : 0.f;
            }
        }
        // Compute chunk kc
        const float* ws = &wbuf[cb][oc];
        const float* vs = &pbuf[cb][pg*4];
        #pragma unroll 16
        for (int jj = 0; jj < CHUNK; jj++) {
            float w = ws[jj*32];
            float4 v = *(const float4*)&vs[jj*PT];
            acc.x = fmaf(w, v.x, acc.x);
            acc.y = fmaf(w, v.y, acc.y);
            acc.z = fmaf(w, v.z, acc.z);
            acc.w = fmaf(w, v.w, acc.w);
        }
        __syncthreads();
    }

    if (oc < NOFF) {
        float bias = (oc < 18) ? b_off[oc] : b_mask[oc-18];
        acc.x += bias; acc.y += bias; acc.z += bias; acc.w += bias;
        if (oc >= 18) {
            acc.x = 1.f / (1.f + __expf(-acc.x));
            acc.y = 1.f / (1.f + __expf(-acc.y));
            acc.z = 1.f / (1.f + __expf(-acc.z));
            acc.w = 1.f / (1.f + __expf(-acc.w));
        }
        int pos = pg*4;
        int row = pos >> 5, col = pos & 31;
        *(float4*)&g_offmask[((size_t)b*NOFF + oc)*HW + (ho0+row)*Ww + wo0 + col] = acc;
    }
}

// ---------------------------------------------------------------------------
// Kernel 2: bilinear gather + 64x576 GEMM, chunked + double-buffered.
// Block: 512 threads, 64 positions (2 rows x 32 cols).
// ---------------------------------------------------------------------------
__global__ void __launch_bounds__(512, 2) deform_main(
        const float* __restrict__ x,
        float* __restrict__ out) {
    __shared__ __align__(16) float vbuf[2][CHUNK*PT];   // 2 x 16KB
    __shared__ __align__(16) float wbuf[2][CHUNK*COUT]; // 2 x 16KB
    __shared__ int    p_y0[K2*PT];
    __shared__ int    p_x0[K2*PT];
    __shared__ float4 p_w [K2*PT];

    const int wo0 = blockIdx.x * 32;
    const int ho0 = blockIdx.y * 2;
    const int b   = blockIdx.z;
    const int tid = threadIdx.x;
    const float* xb = x + (size_t)b * Cc * HW;

    // Phase 0: bilinear parameters for 9 x 64 (k2, pos)
    for (int i = tid; i < K2*PT; i += 512) {
        int pos = i & 63;
        int k2  = i >> 6;
        int ho  = ho0 + (pos>>5);
        int wo  = wo0 + (pos&31);
        const float* om = g_offmask + (size_t)b*NOFF*HW + ho*Ww + wo;
        float dy = om[(2*k2    )*HW];
        float dx = om[(2*k2 + 1)*HW];
        float m  = om[(18 + k2 )*HW];
        int ky = k2 / 3, kx = k2 - ky*3;
        float py = dy + (float)(ho - 1 + ky);
        float px = dx + (float)(wo - 1 + kx);
        float fy = floorf(py);
        float fx = floorf(px);
        float wy1 = py - fy, wx1 = px - fx;
        float wy0 = 1.f - wy1, wx0 = 1.f - wx1;
        p_y0[i] = (int)fy;
        p_x0[i] = (int)fx;
        p_w [i] = make_float4(wy0*wx0*m, wy0*wx1*m, wy1*wx0*m, wy1*wx1*m);
    }
    __syncthreads();

    const int co = tid & 63;
    const int pg = tid >> 6;    // 0..7 -> 8 positions each
    float4 a0 = make_float4(0.f,0.f,0.f,0.f);
    float4 a1 = make_float4(0.f,0.f,0.f,0.f);

    // Prologue: stage chunk 0
    {
        const int jc = 0;
        #pragma unroll
        for (int i = tid; i < CHUNK*PT; i += 512) {
            int pos = i & 63, jj = i >> 6;
            int j = jc*CHUNK + jj;
            int c = j / 9, k2 = j - c*9;
            int pk = k2*PT + pos;
            int y0 = p_y0[pk], x0 = p_x0[pk];
            float4 w = p_w[pk];
            const float* xc = xb + c*HW;
            bool vy0 = (y0   >= 0) && (y0   < Hh);
            bool vy1 = (y0+1 >= 0) && (y0+1 < Hh);
            bool vx0 = (x0   >= 0) && (x0   < Ww);
            bool vx1 = (x0+1 >= 0) && (x0+1 < Ww);
            float v = 0.f;
            if (vy0) { const float* r = xc + y0*Ww;
                if (vx0) v = fmaf(w.x, r[x0],   v);
                if (vx1) v = fmaf(w.y, r[x0+1], v); }
            if (vy1) { const float* r = xc + (y0+1)*Ww;
                if (vx0) v = fmaf(w.z, r[x0],   v);
                if (vx1) v = fmaf(w.w, r[x0+1], v); }
            vbuf[0][jj*PT + pos] = v;
        }
        #pragma unroll
        for (int i = tid; i < CHUNK*COUT/4; i += 512)
            ((float4*)wbuf[0])[i] = ((const float4*)(g_wT + jc*CHUNK*COUT))[i];
    }
    __syncthreads();

    for (int kc = 0; kc < NCHUNK; kc++) {
        int cb = kc & 1, nb = cb ^ 1;
        if (kc + 1 < NCHUNK) {
            const int jc = kc + 1;
            #pragma unroll
            for (int i = tid; i < CHUNK*PT; i += 512) {
                int pos = i & 63, jj = i >> 6;
                int j = jc*CHUNK + jj;
                int c = j / 9, k2 = j - c*9;
                int pk = k2*PT + pos;
                int y0 = p_y0[pk], x0 = p_x0[pk];
                float4 w = p_w[pk];
                const float* xc = xb + c*HW;
                bool vy0 = (y0   >= 0) && (y0   < Hh);
                bool vy1 = (y0+1 >= 0) && (y0+1 < Hh);
                bool vx0 = (x0   >= 0) && (x0   < Ww);
                bool vx1 = (x0+1 >= 0) && (x0+1 < Ww);
                float v = 0.f;
                if (vy0) { const float* r = xc + y0*Ww;
                    if (vx0) v = fmaf(w.x, r[x0],   v);
                    if (vx1) v = fmaf(w.y, r[x0+1], v); }
                if (vy1) { const float* r = xc + (y0+1)*Ww;
                    if (vx0) v = fmaf(w.z, r[x0],   v);
                    if (vx1) v = fmaf(w.w, r[x0+1], v); }
                vbuf[nb][jj*PT + pos] = v;
            }
            #pragma unroll
            for (int i = tid; i < CHUNK*COUT/4; i += 512)
                ((float4*)wbuf[nb])[i] = ((const float4*)(g_wT + jc*CHUNK*COUT))[i];
        }
        // Compute chunk kc
        const float* ws = &wbuf[cb][co];
        const float* vs = &vbuf[cb][pg*8];
        #pragma unroll 16
        for (int jj = 0; jj < CHUNK; jj++) {
            float w = ws[jj*COUT];
            float4 v0 = *(const float4*)&vs[jj*PT];
            float4 v1 = *(const float4*)&vs[jj*PT + 4];
            a0.x = fmaf(w, v0.x, a0.x);
            a0.y = fmaf(w, v0.y, a0.y);
            a0.z = fmaf(w, v0.z, a0.z);
            a0.w = fmaf(w, v0.w, a0.w);
            a1.x = fmaf(w, v1.x, a1.x);
            a1.y = fmaf(w, v1.y, a1.y);
            a1.z = fmaf(w, v1.z, a1.z);
            a1.w = fmaf(w, v1.w, a1.w);
        }
        __syncthreads();
    }

    // Output: pos = pg*8 .. pg*8+7 (all within one 32-col row)
    {
        int pos = pg*8;
        int row = pos >> 5, col = pos & 31;
        float* o = out + ((size_t)b*COUT + co)*HW + (ho0+row)*Ww + wo0 + col;
        *(float4*)o       = a0;
        *(float4*)(o + 4) = a1;
    }
}

// ---------------------------------------------------------------------------
extern "C" void kernel_launch(void* const* d_in, const int* in_sizes, int n_in,
                              void* d_out, int out_size) {
    const float* x      = (const float*)d_in[0];
    const float* w_off  = (const float*)d_in[1];
    const float* b_off  = (const float*)d_in[2];
    const float* w_mask = (const float*)d_in[3];
    const float* b_mask = (const float*)d_in[4];
    const float* w_def  = (const float*)d_in[5];
    float* out = (float*)d_out;

    transpose_weights<<<(Jdim*COUT + 255)/256, 256>>>(w_off, w_mask, w_def);

    dim3 g(Ww/32, Hh/2, Bn);
    offmask_conv<<<g, 512>>>(x, b_off, b_mask);
    deform_main<<<g, 512>>>(x, out);
}